// round 13
// baseline (speedup 1.0000x reference)
#include <cuda_runtime.h>
#include <cuda_fp16.h>
#include <mma.h>
#include <math.h>
#include <cstdint>

using namespace nvcuda;

#define B_SZ   128
#define KDIM   4096
#define EMB    512
#define NNEG   2048
#define OUTW   (NNEG + 1)

#define BK     32
#define LDH    40    // padded half-row (80B, LDSM-friendly, mult of 8)

// Scratch (static device globals — no allocation).
__device__ __half g_parth[8 * B_SZ * KDIM];   // 8 MB (fp16 split-K partials, reused)
__device__ __half g_vfs_h[B_SZ * KDIM];       // 1 MB
__device__ __half g_hidden_h[B_SZ * KDIM];    // 1 MB
__device__ __half g_We_h[EMB * KDIM];         // 4 MB
__device__ __half g_nlfs_h[NNEG * EMB];       // 2 MB
__device__ float  g_emb[B_SZ * EMB];          // 256 KB (f32, for pscore)
__device__ __half g_emb_h[B_SZ * EMB];        // 128 KB (fp16, for nscore)

__device__ __forceinline__ uint32_t h2_bits(__half2 h) {
    return *reinterpret_cast<uint32_t*>(&h);
}
__device__ __forceinline__ __half2 b2h2(uint32_t u) {
    __half2 h; *reinterpret_cast<uint32_t*>(&h) = u; return h;
}
__device__ __forceinline__ uint32_t smem_u32(const void* p) {
    uint32_t a;
    asm("{ .reg .u64 t; cvta.to.shared.u64 t, %1; cvt.u32.u64 %0, t; }" : "=r"(a) : "l"(p));
    return a;
}

// One merged f32->fp16 conversion over vfs (64K grps), W_e (256K), n_lfs (128K).
// 8 elems per thread, 448K threads = 1792 blocks.
__global__ void __launch_bounds__(256) cvt_all(
    const float* __restrict__ vfs, const float* __restrict__ We,
    const float* __restrict__ nlfs,
    __half* __restrict__ vfs_h, __half* __restrict__ We_h, __half* __restrict__ nlfs_h)
{
    int id = blockIdx.x * blockDim.x + threadIdx.x;
    const float* s; __half* d; int off;
    if (id < 65536)        { s = vfs;  d = vfs_h;  off = id; }
    else if (id < 327680)  { s = We;   d = We_h;   off = id - 65536; }
    else                   { s = nlfs; d = nlfs_h; off = id - 327680; }
    const float4* sp = (const float4*)s;
    float4 a = sp[off * 2], b = sp[off * 2 + 1];
    uint4 o;
    o.x = h2_bits(__floats2half2_rn(a.x, a.y));
    o.y = h2_bits(__floats2half2_rn(a.z, a.w));
    o.z = h2_bits(__floats2half2_rn(b.x, b.y));
    o.w = h2_bits(__floats2half2_rn(b.z, b.w));
    ((uint4*)d)[off] = o;
}

// ---------------------------------------------------------------------------
// Staging helpers
// ---------------------------------------------------------------------------
__device__ __forceinline__ void cp_rows16(const __half* __restrict__ G, __half* s,
                                          int k0, int tid, int rowbase)
{
    #pragma unroll
    for (int i = 0; i < 2; i++) {
        int id = tid + i * 256;            // 0..511 16B chunks
        int row = id >> 2;
        int seg = (id & 3) << 3;           // halves
        uint32_t d = smem_u32(&s[row * LDH + seg]);
        const __half* g = &G[(size_t)(rowbase + row) * KDIM + k0 + seg];
        asm volatile("cp.async.cg.shared.global [%0], [%1], 16;" :: "r"(d), "l"(g) : "memory");
    }
}

__device__ __forceinline__ void ldg_cvt_b(uint32_t* rb, const float* __restrict__ B,
                                          int k0, int tid, int nbase)
{
    const int row = tid >> 1;
    const int seg = (tid & 1) << 4;        // 0 or 16 floats
    const float* pb = &B[(size_t)(nbase + row) * KDIM + k0 + seg];
    #pragma unroll
    for (int i = 0; i < 4; i++) {
        float4 vb = *(const float4*)(pb + i * 4);
        rb[i * 2 + 0] = h2_bits(__floats2half2_rn(vb.x, vb.y));
        rb[i * 2 + 1] = h2_bits(__floats2half2_rn(vb.z, vb.w));
    }
}

__device__ __forceinline__ void sts_b(__half* sB, const uint32_t* rb, int tid)
{
    const int row = tid >> 1;
    const int seg = (tid & 1) << 4;
    *(uint4*)&sB[row * LDH + seg]     = make_uint4(rb[0], rb[1], rb[2], rb[3]);
    *(uint4*)&sB[row * LDH + seg + 8] = make_uint4(rb[4], rb[5], rb[6], rb[7]);
}

// WMMA compute tile
__device__ __forceinline__ void mma_tile(
    wmma::fragment<wmma::accumulator, 16, 16, 16, float> (&acc)[4][2],
    const __half* sA, const __half* sB, int wm, int wn)
{
    #pragma unroll
    for (int ks = 0; ks < 2; ks++) {
        const int k0 = ks * 16;
        wmma::fragment<wmma::matrix_a, 16, 16, 16, __half, wmma::row_major> af[4];
        wmma::fragment<wmma::matrix_b, 16, 16, 16, __half, wmma::col_major> bf[2];
        #pragma unroll
        for (int i = 0; i < 4; i++)
            wmma::load_matrix_sync(af[i], &sA[(wm * 64 + i * 16) * LDH + k0], LDH);
        #pragma unroll
        for (int j = 0; j < 2; j++)
            wmma::load_matrix_sync(bf[j], &sB[(wn * 32 + j * 16) * LDH + k0], LDH);
        #pragma unroll
        for (int i = 0; i < 4; i++)
            #pragma unroll
            for (int j = 0; j < 2; j++)
                wmma::mma_sync(acc[i][j], af[i], bf[j], acc[i][j]);
    }
}

// Epilogue: f32 acc -> fp16 partial store via SMEM (2 passes of 128x64 f32).
__device__ __forceinline__ void epilogue_f16(
    wmma::fragment<wmma::accumulator, 16, 16, 16, float> (&acc)[4][2],
    float* sred, __half* __restrict__ Cout, int ldc, int nbase,
    int wm, int wn, int tid)
{
    #pragma unroll
    for (int j = 0; j < 2; j++) {
        __syncthreads();
        #pragma unroll
        for (int i = 0; i < 4; i++)
            wmma::store_matrix_sync(&sred[(wm * 64 + i * 16) * 64 + wn * 16],
                                    acc[i][j], 64, wmma::mem_row_major);
        __syncthreads();
        const int row = tid >> 1;
        const int c0 = (tid & 1) * 32;
        const float* p = &sred[row * 64 + c0];
        #pragma unroll
        for (int s = 0; s < 2; s++) {
            const float* q = p + s * 16;
            uint4 w0, w1;
            w0.x = h2_bits(__floats2half2_rn(q[0],  q[1]));
            w0.y = h2_bits(__floats2half2_rn(q[2],  q[3]));
            w0.z = h2_bits(__floats2half2_rn(q[4],  q[5]));
            w0.w = h2_bits(__floats2half2_rn(q[6],  q[7]));
            w1.x = h2_bits(__floats2half2_rn(q[8],  q[9]));
            w1.y = h2_bits(__floats2half2_rn(q[10], q[11]));
            w1.z = h2_bits(__floats2half2_rn(q[12], q[13]));
            w1.w = h2_bits(__floats2half2_rn(q[14], q[15]));
            const int strip = (c0 >> 4) + s;                 // 0..3
            const int gcol = nbase + strip * 32 + j * 16;
            *(uint4*)&Cout[(size_t)row * ldc + gcol]     = w0;
            *(uint4*)&Cout[(size_t)row * ldc + gcol + 8] = w1;
        }
    }
}

// GEMM1: A fp16 via cp.async, B f32 via LDG->cvt->STS. fp16 partials out.
__global__ void __launch_bounds__(256, 2)
hgemm(const __half* __restrict__ A, const float* __restrict__ B,
      __half* __restrict__ C, int ldc, int k_len)
{
    __shared__ __align__(16) char smem_raw[4 * 128 * LDH * 2];   // 40960 B
    __half* sAb = (__half*)smem_raw;
    __half* sBb = sAb + 2 * 128 * LDH;

    const int tid = threadIdx.x;
    const int wid = tid >> 5;
    const int wm = wid >> 2, wn = wid & 3;
    const int nbase = blockIdx.x * 128;
    const int k_lo = blockIdx.y * k_len;
    __half* __restrict__ Cout = C + (size_t)blockIdx.y * 128u * (size_t)ldc;

    wmma::fragment<wmma::accumulator, 16, 16, 16, float> acc[4][2];
    #pragma unroll
    for (int i = 0; i < 4; i++)
        #pragma unroll
        for (int j = 0; j < 2; j++) wmma::fill_fragment(acc[i][j], 0.0f);

    const int nIter = k_len / BK;
    uint32_t rb[8];

    cp_rows16(A, sAb, k_lo, tid, 0);
    asm volatile("cp.async.commit_group;" ::: "memory");
    ldg_cvt_b(rb, B, k_lo, tid, nbase);
    sts_b(sBb, rb, tid);
    asm volatile("cp.async.wait_group 0;" ::: "memory");
    __syncthreads();

    for (int it = 0; it < nIter; it++) {
        const int p = it & 1;
        if (it + 1 < nIter) {
            cp_rows16(A, sAb + (p ^ 1) * 128 * LDH, k_lo + (it + 1) * BK, tid, 0);
            asm volatile("cp.async.commit_group;" ::: "memory");
            ldg_cvt_b(rb, B, k_lo + (it + 1) * BK, tid, nbase);
        }
        mma_tile(acc, sAb + p * 128 * LDH, sBb + p * 128 * LDH, wm, wn);
        if (it + 1 < nIter) {
            sts_b(sBb + (p ^ 1) * 128 * LDH, rb, tid);
            asm volatile("cp.async.wait_group 0;" ::: "memory");
            __syncthreads();
        }
    }

    epilogue_f16(acc, (float*)smem_raw, Cout, ldc, nbase, wm, wn, tid);
}

// GEMM2: both operands fp16 via cp.async. fp16 partials out.
__global__ void __launch_bounds__(256, 2)
hgemm_hh(const __half* __restrict__ A, const __half* __restrict__ B,
         __half* __restrict__ C, int ldc, int k_len)
{
    __shared__ __align__(16) char smem_raw[4 * 128 * LDH * 2];   // 40960 B
    __half* sAb = (__half*)smem_raw;
    __half* sBb = sAb + 2 * 128 * LDH;

    const int tid = threadIdx.x;
    const int wid = tid >> 5;
    const int wm = wid >> 2, wn = wid & 3;
    const int nbase = blockIdx.x * 128;
    const int k_lo = blockIdx.y * k_len;
    __half* __restrict__ Cout = C + (size_t)blockIdx.y * 128u * (size_t)ldc;

    wmma::fragment<wmma::accumulator, 16, 16, 16, float> acc[4][2];
    #pragma unroll
    for (int i = 0; i < 4; i++)
        #pragma unroll
        for (int j = 0; j < 2; j++) wmma::fill_fragment(acc[i][j], 0.0f);

    const int nIter = k_len / BK;

    cp_rows16(A, sAb, k_lo, tid, 0);
    cp_rows16(B, sBb, k_lo, tid, nbase);
    asm volatile("cp.async.commit_group;" ::: "memory");
    asm volatile("cp.async.wait_group 0;" ::: "memory");
    __syncthreads();

    for (int it = 0; it < nIter; it++) {
        const int p = it & 1;
        if (it + 1 < nIter) {
            cp_rows16(A, sAb + (p ^ 1) * 128 * LDH, k_lo + (it + 1) * BK, tid, 0);
            cp_rows16(B, sBb + (p ^ 1) * 128 * LDH, k_lo + (it + 1) * BK, tid, nbase);
            asm volatile("cp.async.commit_group;" ::: "memory");
        }
        mma_tile(acc, sAb + p * 128 * LDH, sBb + p * 128 * LDH, wm, wn);
        if (it + 1 < nIter) {
            asm volatile("cp.async.wait_group 0;" ::: "memory");
            __syncthreads();
        }
    }

    epilogue_f16(acc, (float*)smem_raw, Cout, ldc, nbase, wm, wn, tid);
}

// hidden(fp16) = sum_{sk<8} parth[sk] + b_h.  8 dims/thread, 256 blocks.
__global__ void __launch_bounds__(256) reduce_hidden(const float* __restrict__ b_h) {
    int o = blockIdx.x * blockDim.x + threadIdx.x;     // < 65536 (8-dim groups)
    float s[8] = {};
    #pragma unroll
    for (int k = 0; k < 8; k++) {
        uint4 v = *(const uint4*)&g_parth[(size_t)k * (B_SZ * KDIM) + (size_t)o * 8];
        float2 f;
        f = __half22float2(b2h2(v.x)); s[0] += f.x; s[1] += f.y;
        f = __half22float2(b2h2(v.y)); s[2] += f.x; s[3] += f.y;
        f = __half22float2(b2h2(v.z)); s[4] += f.x; s[5] += f.y;
        f = __half22float2(b2h2(v.w)); s[6] += f.x; s[7] += f.y;
    }
    int d0 = (o * 8) & (KDIM - 1);
    float4 b0 = *(const float4*)&b_h[d0];
    float4 b1 = *(const float4*)&b_h[d0 + 4];
    uint4 w;
    w.x = h2_bits(__floats2half2_rn(s[0] + b0.x, s[1] + b0.y));
    w.y = h2_bits(__floats2half2_rn(s[2] + b0.z, s[3] + b0.w));
    w.z = h2_bits(__floats2half2_rn(s[4] + b1.x, s[5] + b1.y));
    w.w = h2_bits(__floats2half2_rn(s[6] + b1.z, s[7] + b1.w));
    ((uint4*)g_hidden_h)[o] = w;
}

// emb = sum_{sk<32} parth[sk] + b_e.  4 dims/thread, 64 blocks.
__global__ void __launch_bounds__(256) reduce_emb(const float* __restrict__ b_e) {
    int o = blockIdx.x * blockDim.x + threadIdx.x;     // < 16384 (4-dim groups)
    float s[4] = {};
    #pragma unroll
    for (int k = 0; k < 32; k++) {
        uint2 v = *(const uint2*)&g_parth[(size_t)k * (B_SZ * EMB) + (size_t)o * 4];
        float2 f;
        f = __half22float2(b2h2(v.x)); s[0] += f.x; s[1] += f.y;
        f = __half22float2(b2h2(v.y)); s[2] += f.x; s[3] += f.y;
    }
    float4 bias = *(const float4*)&b_e[(o * 4) & (EMB - 1)];
    float4 r = make_float4(s[0] + bias.x, s[1] + bias.y, s[2] + bias.z, s[3] + bias.w);
    ((float4*)g_emb)[o] = r;
    uint2 hh;
    hh.x = h2_bits(__floats2half2_rn(r.x, r.y));
    hh.y = h2_bits(__floats2half2_rn(r.z, r.w));
    ((uint2*)g_emb_h)[o] = hh;
}

// out[b, 1+n] = -||relu(n - emb)||  (fp16 half2 math, f32 chunk accumulation);
// blocks with bx==16 do positive scores in f32.
__global__ void __launch_bounds__(256, 2)
nscore_kernel(const float* __restrict__ p_lfs, float* __restrict__ out) {
    const int tid = threadIdx.x;
    const int btile = blockIdx.y * 16;

    if (blockIdx.x == 16) {   // positive-score path: 8 warps x 2 b each (f32)
        int wq = tid >> 5, lane = tid & 31;
        #pragma unroll
        for (int r = 0; r < 2; r++) {
            int b = btile + wq * 2 + r;
            const float* pp = p_lfs + (size_t)b * EMB;
            const float* ee = g_emb + (size_t)b * EMB;
            float s = 0.f;
            #pragma unroll
            for (int j = 0; j < 4; j++) {
                int d = j * 128 + lane * 4;
                float4 p = *(const float4*)&pp[d];
                float4 e = *(const float4*)&ee[d];
                float r0 = fmaxf(p.x - e.x, 0.f), r1 = fmaxf(p.y - e.y, 0.f);
                float r2 = fmaxf(p.z - e.z, 0.f), r3 = fmaxf(p.w - e.w, 0.f);
                s = fmaf(r0, r0, s); s = fmaf(r1, r1, s);
                s = fmaf(r2, r2, s); s = fmaf(r3, r3, s);
            }
            #pragma unroll
            for (int off = 16; off > 0; off >>= 1) s += __shfl_down_sync(0xffffffffu, s, off);
            if (lane == 0) out[(size_t)b * OUTW] = -sqrtf(s);
        }
        return;
    }

    __shared__ __half2 Ns2[16][132];   // [d-pair][n]
    __shared__ __half2 Es2[16][16];    // [b][d-pair]
    const int tx = tid & 31;
    const int bq = tid >> 5;
    const int nbase = blockIdx.x * 128;

    float facc[2][4] = {};
    uint4 nR[2];
    uint2 eR = make_uint2(0u, 0u);
    const int erow = tid >> 3, edp = (tid & 7) * 2;    // Es: 16 rows x 8 thr

    #pragma unroll
    for (int i = 0; i < 2; i++) {
        int f = tid + i * 256;
        int row = f >> 2, seg = (f & 3) * 8;           // dims
        nR[i] = *(const uint4*)&g_nlfs_h[(size_t)(nbase + row) * EMB + seg];
    }
    if (tid < 128)
        eR = *(const uint2*)&g_emb_h[(size_t)(btile + erow) * EMB + edp * 2];

    for (int it = 0; it < 16; it++) {
        #pragma unroll
        for (int i = 0; i < 2; i++) {
            int f = tid + i * 256;
            int row = f >> 2, dp0 = (f & 3) * 4;
            Ns2[dp0 + 0][row] = b2h2(nR[i].x);
            Ns2[dp0 + 1][row] = b2h2(nR[i].y);
            Ns2[dp0 + 2][row] = b2h2(nR[i].z);
            Ns2[dp0 + 3][row] = b2h2(nR[i].w);
        }
        if (tid < 128) {
            Es2[erow][edp]     = b2h2(eR.x);
            Es2[erow][edp + 1] = b2h2(eR.y);
        }
        __syncthreads();
        if (it + 1 < 16) {
            int dc = (it + 1) * 32;
            #pragma unroll
            for (int i = 0; i < 2; i++) {
                int f = tid + i * 256;
                int row = f >> 2, seg = (f & 3) * 8;
                nR[i] = *(const uint4*)&g_nlfs_h[(size_t)(nbase + row) * EMB + dc + seg];
            }
            if (tid < 128)
                eR = *(const uint2*)&g_emb_h[(size_t)(btile + erow) * EMB + dc + edp * 2];
        }

        const __half2 hz = __float2half2_rn(0.f);
        __half2 hacc[2][4];
        #pragma unroll
        for (int i = 0; i < 2; i++)
            #pragma unroll
            for (int j = 0; j < 4; j++) hacc[i][j] = hz;

        #pragma unroll
        for (int d = 0; d < 16; d++) {
            __half2 e0 = Es2[bq * 2 + 0][d];
            __half2 e1 = Es2[bq * 2 + 1][d];
            uint4 nv = *(const uint4*)&Ns2[d][tx * 4];
            __half2 n0 = b2h2(nv.x), n1 = b2h2(nv.y), n2 = b2h2(nv.z), n3 = b2h2(nv.w);
            __half2 t;
            t = __hmax2(__hsub2(n0, e0), hz); hacc[0][0] = __hfma2(t, t, hacc[0][0]);
            t = __hmax2(__hsub2(n1, e0), hz); hacc[0][1] = __hfma2(t, t, hacc[0][1]);
            t = __hmax2(__hsub2(n2, e0), hz); hacc[0][2] = __hfma2(t, t, hacc[0][2]);
            t = __hmax2(__hsub2(n3, e0), hz); hacc[0][3] = __hfma2(t, t, hacc[0][3]);
            t = __hmax2(__hsub2(n0, e1), hz); hacc[1][0] = __hfma2(t, t, hacc[1][0]);
            t = __hmax2(__hsub2(n1, e1), hz); hacc[1][1] = __hfma2(t, t, hacc[1][1]);
            t = __hmax2(__hsub2(n2, e1), hz); hacc[1][2] = __hfma2(t, t, hacc[1][2]);
            t = __hmax2(__hsub2(n3, e1), hz); hacc[1][3] = __hfma2(t, t, hacc[1][3]);
        }
        __syncthreads();

        #pragma unroll
        for (int i = 0; i < 2; i++)
            #pragma unroll
            for (int j = 0; j < 4; j++) {
                float2 f = __half22float2(hacc[i][j]);
                facc[i][j] += f.x + f.y;
            }
    }

    #pragma unroll
    for (int bi = 0; bi < 2; bi++) {
        int b = btile + bq * 2 + bi;
        #pragma unroll
        for (int j = 0; j < 4; j++)
            out[(size_t)b * OUTW + 1 + nbase + tx * 4 + j] = -sqrtf(facc[bi][j]);
    }
}

extern "C" void kernel_launch(void* const* d_in, const int* in_sizes, int n_in,
                              void* d_out, int out_size) {
    const float* vfs   = (const float*)d_in[0];
    const float* p_lfs = (const float*)d_in[1];
    const float* n_lfs = (const float*)d_in[2];
    const float* W_h   = (const float*)d_in[3];
    const float* b_h   = (const float*)d_in[4];
    const float* W_e   = (const float*)d_in[5];
    const float* b_e   = (const float*)d_in[6];
    float* out = (float*)d_out;

    __half *parth = nullptr, *vfs_h = nullptr, *hidden_h = nullptr;
    __half *We_h = nullptr, *nlfs_h = nullptr;
    cudaGetSymbolAddress((void**)&parth, g_parth);
    cudaGetSymbolAddress((void**)&vfs_h, g_vfs_h);
    cudaGetSymbolAddress((void**)&hidden_h, g_hidden_h);
    cudaGetSymbolAddress((void**)&We_h, g_We_h);
    cudaGetSymbolAddress((void**)&nlfs_h, g_nlfs_h);

    // merged fp16 pre-conversion (1 launch)
    cvt_all<<<1792, 256>>>(vfs, W_e, n_lfs, vfs_h, We_h, nlfs_h);
    // GEMM1: parth[8][128][4096] = vfs_h @ W_h^T  (K-split 8 -> 256 CTAs)
    hgemm<<<dim3(KDIM / 128, 8), 256>>>(vfs_h, W_h, parth, KDIM, KDIM / 8);
    reduce_hidden<<<256, 256>>>(b_h);
    // GEMM2: parth[32][128][512] = hidden_h @ We_h^T (K-split 32 -> 128 CTAs)
    hgemm_hh<<<dim3(EMB / 128, 32), 256>>>(hidden_h, We_h, parth, EMB, KDIM / 32);
    reduce_emb<<<64, 256>>>(b_e);
    // scores (bx==16 blocks do positive scores)
    nscore_kernel<<<dim3(NNEG / 128 + 1, B_SZ / 16), 256>>>(p_lfs, out);
}

// round 14
// speedup vs baseline: 1.1122x; 1.1122x over previous
#include <cuda_runtime.h>
#include <cuda_fp16.h>
#include <mma.h>
#include <math.h>
#include <cstdint>

using namespace nvcuda;

#define B_SZ   128
#define KDIM   4096
#define EMB    512
#define NNEG   2048
#define OUTW   (NNEG + 1)

#define BK     32
#define LDH    40    // padded half-row (80B, LDSM-friendly, mult of 8)

// Scratch (static device globals — no allocation).
__device__ float  g_part[4 * 1024 * 1024];    // 16 MB (f32 split-K partials, reused)
__device__ __half g_vfs_h[B_SZ * KDIM];       // 1 MB
__device__ __half g_hidden_h[B_SZ * KDIM];    // 1 MB
__device__ __half g_nlfs_h[NNEG * EMB];       // 2 MB
__device__ float  g_emb[B_SZ * EMB];          // 256 KB (f32, for pscore)
__device__ __half g_emb_h[B_SZ * EMB];        // 128 KB (fp16, for nscore)

__device__ __forceinline__ uint32_t h2_bits(__half2 h) {
    return *reinterpret_cast<uint32_t*>(&h);
}
__device__ __forceinline__ __half2 b2h2(uint32_t u) {
    __half2 h; *reinterpret_cast<uint32_t*>(&h) = u; return h;
}
__device__ __forceinline__ uint32_t smem_u32(const void* p) {
    uint32_t a;
    asm("{ .reg .u64 t; cvta.to.shared.u64 t, %1; cvt.u32.u64 %0, t; }" : "=r"(a) : "l"(p));
    return a;
}

// One merged f32->fp16 conversion over vfs (65536 grps of 8) + n_lfs (131072).
__global__ void __launch_bounds__(256) cvt_all(
    const float* __restrict__ vfs, const float* __restrict__ nlfs,
    __half* __restrict__ vfs_h, __half* __restrict__ nlfs_h)
{
    int id = blockIdx.x * blockDim.x + threadIdx.x;     // < 196608
    const float* s; __half* d; int off;
    if (id < 65536) { s = vfs;  d = vfs_h;  off = id; }
    else            { s = nlfs; d = nlfs_h; off = id - 65536; }
    const float4* sp = (const float4*)s;
    float4 a = sp[off * 2], b = sp[off * 2 + 1];
    uint4 o;
    o.x = h2_bits(__floats2half2_rn(a.x, a.y));
    o.y = h2_bits(__floats2half2_rn(a.z, a.w));
    o.z = h2_bits(__floats2half2_rn(b.x, b.y));
    o.w = h2_bits(__floats2half2_rn(b.z, b.w));
    ((uint4*)d)[off] = o;
}

// ---------------------------------------------------------------------------
// fp16 WMMA split-K GEMM: A fp16 via cp.async, B f32 via LDG->cvt->STS,
// f32 accumulate + direct f32 partial store. 2 CTAs/SM.
// Cpart[sk][128, N] = A[128, ksl] @ B[N, ksl]^T
// BM=128, BN=128, BK=32, 256 threads (8 warps 2x4), warp tile 64x32.
// ---------------------------------------------------------------------------
__device__ __forceinline__ void cp_A(const __half* __restrict__ A, __half* sA,
                                     int k0, int tid)
{
    #pragma unroll
    for (int i = 0; i < 2; i++) {
        int id = tid + i * 256;            // 0..511 16B chunks
        int row = id >> 2;
        int seg = (id & 3) << 3;           // halves
        uint32_t d = smem_u32(&sA[row * LDH + seg]);
        const __half* g = &A[(size_t)row * KDIM + k0 + seg];
        asm volatile("cp.async.cg.shared.global [%0], [%1], 16;" :: "r"(d), "l"(g) : "memory");
    }
}

__device__ __forceinline__ void ldg_cvt_b(uint32_t* rb, const float* __restrict__ B,
                                          int k0, int tid, int nbase)
{
    const int row = tid >> 1;
    const int seg = (tid & 1) << 4;        // 0 or 16 floats
    const float* pb = &B[(size_t)(nbase + row) * KDIM + k0 + seg];
    #pragma unroll
    for (int i = 0; i < 4; i++) {
        float4 vb = *(const float4*)(pb + i * 4);
        rb[i * 2 + 0] = h2_bits(__floats2half2_rn(vb.x, vb.y));
        rb[i * 2 + 1] = h2_bits(__floats2half2_rn(vb.z, vb.w));
    }
}

__device__ __forceinline__ void sts_b(__half* sB, const uint32_t* rb, int tid)
{
    const int row = tid >> 1;
    const int seg = (tid & 1) << 4;
    *(uint4*)&sB[row * LDH + seg]     = make_uint4(rb[0], rb[1], rb[2], rb[3]);
    *(uint4*)&sB[row * LDH + seg + 8] = make_uint4(rb[4], rb[5], rb[6], rb[7]);
}

__global__ void __launch_bounds__(256, 2)
hgemm(const __half* __restrict__ A, const float* __restrict__ B,
      float* __restrict__ C, int ldc, int k_len)
{
    __shared__ __align__(16) __half sA[2][128 * LDH];
    __shared__ __align__(16) __half sB[2][128 * LDH];

    const int tid = threadIdx.x;
    const int wid = tid >> 5;
    const int wm = wid >> 2, wn = wid & 3;
    const int nbase = blockIdx.x * 128;
    const int k_lo = blockIdx.y * k_len;
    float* __restrict__ Cout = C + (size_t)blockIdx.y * 128u * (size_t)ldc;

    wmma::fragment<wmma::accumulator, 16, 16, 16, float> acc[4][2];
    #pragma unroll
    for (int i = 0; i < 4; i++)
        #pragma unroll
        for (int j = 0; j < 2; j++) wmma::fill_fragment(acc[i][j], 0.0f);

    const int nIter = k_len / BK;
    uint32_t rb[8];

    cp_A(A, sA[0], k_lo, tid);
    asm volatile("cp.async.commit_group;" ::: "memory");
    ldg_cvt_b(rb, B, k_lo, tid, nbase);
    sts_b(sB[0], rb, tid);
    asm volatile("cp.async.wait_group 0;" ::: "memory");
    __syncthreads();

    for (int it = 0; it < nIter; it++) {
        const int p = it & 1;
        if (it + 1 < nIter) {
            cp_A(A, sA[p ^ 1], k_lo + (it + 1) * BK, tid);
            asm volatile("cp.async.commit_group;" ::: "memory");
            ldg_cvt_b(rb, B, k_lo + (it + 1) * BK, tid, nbase);
        }

        #pragma unroll
        for (int ks = 0; ks < 2; ks++) {
            const int k0 = ks * 16;
            wmma::fragment<wmma::matrix_a, 16, 16, 16, __half, wmma::row_major> af[4];
            wmma::fragment<wmma::matrix_b, 16, 16, 16, __half, wmma::col_major> bf[2];
            #pragma unroll
            for (int i = 0; i < 4; i++)
                wmma::load_matrix_sync(af[i], &sA[p][(wm * 64 + i * 16) * LDH + k0], LDH);
            #pragma unroll
            for (int j = 0; j < 2; j++)
                wmma::load_matrix_sync(bf[j], &sB[p][(wn * 32 + j * 16) * LDH + k0], LDH);
            #pragma unroll
            for (int i = 0; i < 4; i++)
                #pragma unroll
                for (int j = 0; j < 2; j++)
                    wmma::mma_sync(acc[i][j], af[i], bf[j], acc[i][j]);
        }

        if (it + 1 < nIter) {
            sts_b(sB[p ^ 1], rb, tid);
            asm volatile("cp.async.wait_group 0;" ::: "memory");
            __syncthreads();
        }
    }

    #pragma unroll
    for (int i = 0; i < 4; i++)
        #pragma unroll
        for (int j = 0; j < 2; j++)
            wmma::store_matrix_sync(&Cout[(size_t)(wm * 64 + i * 16) * ldc + nbase + wn * 32 + j * 16],
                                    acc[i][j], ldc, wmma::mem_row_major);
}

// hidden(fp16) = sum_{sk<8} part[sk] + b_h.
__global__ void __launch_bounds__(256) reduce_hidden(const float* __restrict__ b_h) {
    int g = blockIdx.x * blockDim.x + threadIdx.x;     // < 262144
    int o = g >> 1, h = g & 1;
    float4 s = make_float4(0.f, 0.f, 0.f, 0.f);
    #pragma unroll
    for (int k = 0; k < 4; k++) {
        float4 v = *(const float4*)&g_part[(size_t)(h * 4 + k) * (B_SZ * KDIM) + (size_t)o * 4];
        s.x += v.x; s.y += v.y; s.z += v.z; s.w += v.w;
    }
    float4 oth;
    oth.x = __shfl_xor_sync(0xffffffffu, s.x, 1);
    oth.y = __shfl_xor_sync(0xffffffffu, s.y, 1);
    oth.z = __shfl_xor_sync(0xffffffffu, s.z, 1);
    oth.w = __shfl_xor_sync(0xffffffffu, s.w, 1);
    if (h == 0) {
        float4 bias = ((const float4*)b_h)[o & (KDIM / 4 - 1)];
        uint2 w;
        w.x = h2_bits(__floats2half2_rn(s.x + oth.x + bias.x, s.y + oth.y + bias.y));
        w.y = h2_bits(__floats2half2_rn(s.z + oth.z + bias.z, s.w + oth.w + bias.w));
        ((uint2*)g_hidden_h)[o] = w;
    }
}

// emb = sum_{sk<32} part[sk] + b_e.  Writes f32 (pscore) and fp16 (nscore).
__global__ void __launch_bounds__(256) reduce_emb(const float* __restrict__ b_e) {
    __shared__ float4 red[8][32];
    const int lane = threadIdx.x & 31;
    const int w = threadIdx.x >> 5;
    const int o = blockIdx.x * 32 + lane;
    float4 s = make_float4(0.f, 0.f, 0.f, 0.f);
    #pragma unroll
    for (int k = 0; k < 4; k++) {
        float4 v = *(const float4*)&g_part[(size_t)(w * 4 + k) * (B_SZ * EMB) + (size_t)o * 4];
        s.x += v.x; s.y += v.y; s.z += v.z; s.w += v.w;
    }
    red[w][lane] = s;
    __syncthreads();
    if (w == 0) {
        float4 r = ((const float4*)b_e)[o & (EMB / 4 - 1)];
        #pragma unroll
        for (int k = 0; k < 8; k++) {
            float4 v = red[k][lane];
            r.x += v.x; r.y += v.y; r.z += v.z; r.w += v.w;
        }
        ((float4*)g_emb)[o] = r;
        uint2 hh;
        hh.x = h2_bits(__floats2half2_rn(r.x, r.y));
        hh.y = h2_bits(__floats2half2_rn(r.z, r.w));
        ((uint2*)g_emb_h)[o] = hh;
    }
}

// out[b, 1+n] = -||relu(n - emb)||  (fp16 half2 math, f32 chunk accumulation);
// blocks with bx==16 do positive scores in f32.
__global__ void __launch_bounds__(256, 2)
nscore_kernel(const float* __restrict__ p_lfs, float* __restrict__ out) {
    const int tid = threadIdx.x;
    const int btile = blockIdx.y * 16;

    if (blockIdx.x == 16) {   // positive-score path: 8 warps x 2 b each (f32)
        int wq = tid >> 5, lane = tid & 31;
        #pragma unroll
        for (int r = 0; r < 2; r++) {
            int b = btile + wq * 2 + r;
            const float* pp = p_lfs + (size_t)b * EMB;
            const float* ee = g_emb + (size_t)b * EMB;
            float s = 0.f;
            #pragma unroll
            for (int j = 0; j < 4; j++) {
                int d = j * 128 + lane * 4;
                float4 p = *(const float4*)&pp[d];
                float4 e = *(const float4*)&ee[d];
                float r0 = fmaxf(p.x - e.x, 0.f), r1 = fmaxf(p.y - e.y, 0.f);
                float r2 = fmaxf(p.z - e.z, 0.f), r3 = fmaxf(p.w - e.w, 0.f);
                s = fmaf(r0, r0, s); s = fmaf(r1, r1, s);
                s = fmaf(r2, r2, s); s = fmaf(r3, r3, s);
            }
            #pragma unroll
            for (int off = 16; off > 0; off >>= 1) s += __shfl_down_sync(0xffffffffu, s, off);
            if (lane == 0) out[(size_t)b * OUTW] = -sqrtf(s);
        }
        return;
    }

    __shared__ __half2 Ns2[16][132];   // [d-pair][n]
    __shared__ __half2 Es2[16][16];    // [b][d-pair]
    const int tx = tid & 31;
    const int bq = tid >> 5;
    const int nbase = blockIdx.x * 128;

    float facc[2][4] = {};
    uint4 nR[2];
    uint2 eR = make_uint2(0u, 0u);
    const int erow = tid >> 3, edp = (tid & 7) * 2;    // Es: 16 rows x 8 thr

    #pragma unroll
    for (int i = 0; i < 2; i++) {
        int f = tid + i * 256;
        int row = f >> 2, seg = (f & 3) * 8;           // dims
        nR[i] = *(const uint4*)&g_nlfs_h[(size_t)(nbase + row) * EMB + seg];
    }
    if (tid < 128)
        eR = *(const uint2*)&g_emb_h[(size_t)(btile + erow) * EMB + edp * 2];

    for (int it = 0; it < 16; it++) {
        #pragma unroll
        for (int i = 0; i < 2; i++) {
            int f = tid + i * 256;
            int row = f >> 2, dp0 = (f & 3) * 4;
            Ns2[dp0 + 0][row] = b2h2(nR[i].x);
            Ns2[dp0 + 1][row] = b2h2(nR[i].y);
            Ns2[dp0 + 2][row] = b2h2(nR[i].z);
            Ns2[dp0 + 3][row] = b2h2(nR[i].w);
        }
        if (tid < 128) {
            Es2[erow][edp]     = b2h2(eR.x);
            Es2[erow][edp + 1] = b2h2(eR.y);
        }
        __syncthreads();
        if (it + 1 < 16) {
            int dc = (it + 1) * 32;
            #pragma unroll
            for (int i = 0; i < 2; i++) {
                int f = tid + i * 256;
                int row = f >> 2, seg = (f & 3) * 8;
                nR[i] = *(const uint4*)&g_nlfs_h[(size_t)(nbase + row) * EMB + dc + seg];
            }
            if (tid < 128)
                eR = *(const uint2*)&g_emb_h[(size_t)(btile + erow) * EMB + dc + edp * 2];
        }

        const __half2 hz = __float2half2_rn(0.f);
        __half2 hacc[2][4];
        #pragma unroll
        for (int i = 0; i < 2; i++)
            #pragma unroll
            for (int j = 0; j < 4; j++) hacc[i][j] = hz;

        #pragma unroll
        for (int d = 0; d < 16; d++) {
            __half2 e0 = Es2[bq * 2 + 0][d];
            __half2 e1 = Es2[bq * 2 + 1][d];
            uint4 nv = *(const uint4*)&Ns2[d][tx * 4];
            __half2 n0 = b2h2(nv.x), n1 = b2h2(nv.y), n2 = b2h2(nv.z), n3 = b2h2(nv.w);
            __half2 t;
            t = __hmax2(__hsub2(n0, e0), hz); hacc[0][0] = __hfma2(t, t, hacc[0][0]);
            t = __hmax2(__hsub2(n1, e0), hz); hacc[0][1] = __hfma2(t, t, hacc[0][1]);
            t = __hmax2(__hsub2(n2, e0), hz); hacc[0][2] = __hfma2(t, t, hacc[0][2]);
            t = __hmax2(__hsub2(n3, e0), hz); hacc[0][3] = __hfma2(t, t, hacc[0][3]);
            t = __hmax2(__hsub2(n0, e1), hz); hacc[1][0] = __hfma2(t, t, hacc[1][0]);
            t = __hmax2(__hsub2(n1, e1), hz); hacc[1][1] = __hfma2(t, t, hacc[1][1]);
            t = __hmax2(__hsub2(n2, e1), hz); hacc[1][2] = __hfma2(t, t, hacc[1][2]);
            t = __hmax2(__hsub2(n3, e1), hz); hacc[1][3] = __hfma2(t, t, hacc[1][3]);
        }
        __syncthreads();

        #pragma unroll
        for (int i = 0; i < 2; i++)
            #pragma unroll
            for (int j = 0; j < 4; j++) {
                float2 f = __half22float2(hacc[i][j]);
                facc[i][j] += f.x + f.y;
            }
    }

    #pragma unroll
    for (int bi = 0; bi < 2; bi++) {
        int b = btile + bq * 2 + bi;
        #pragma unroll
        for (int j = 0; j < 4; j++)
            out[(size_t)b * OUTW + 1 + nbase + tx * 4 + j] = -sqrtf(facc[bi][j]);
    }
}

extern "C" void kernel_launch(void* const* d_in, const int* in_sizes, int n_in,
                              void* d_out, int out_size) {
    const float* vfs   = (const float*)d_in[0];
    const float* p_lfs = (const float*)d_in[1];
    const float* n_lfs = (const float*)d_in[2];
    const float* W_h   = (const float*)d_in[3];
    const float* b_h   = (const float*)d_in[4];
    const float* W_e   = (const float*)d_in[5];
    const float* b_e   = (const float*)d_in[6];
    float* out = (float*)d_out;

    float* part = nullptr;
    __half *vfs_h = nullptr, *hidden_h = nullptr, *nlfs_h = nullptr;
    cudaGetSymbolAddress((void**)&part, g_part);
    cudaGetSymbolAddress((void**)&vfs_h, g_vfs_h);
    cudaGetSymbolAddress((void**)&hidden_h, g_hidden_h);
    cudaGetSymbolAddress((void**)&nlfs_h, g_nlfs_h);

    // merged fp16 pre-conversion: vfs + n_lfs (1 launch, 768 blocks)
    cvt_all<<<768, 256>>>(vfs, n_lfs, vfs_h, nlfs_h);
    // GEMM1: part[8][128][4096] = vfs_h @ W_h^T  (K-split 8 -> 256 CTAs)
    hgemm<<<dim3(KDIM / 128, 8), 256>>>(vfs_h, W_h, part, KDIM, KDIM / 8);
    reduce_hidden<<<1024, 256>>>(b_h);
    // GEMM2: part[32][128][512] = hidden_h @ W_e^T (K-split 32 -> 128 CTAs)
    hgemm<<<dim3(EMB / 128, 32), 256>>>(hidden_h, W_e, part, EMB, KDIM / 32);
    reduce_emb<<<512, 256>>>(b_e);
    // scores (bx==16 blocks do positive scores)
    nscore_kernel<<<dim3(NNEG / 128 + 1, B_SZ / 16), 256>>>(p_lfs, out);
}

// round 15
// speedup vs baseline: 1.2241x; 1.1006x over previous
#include <cuda_runtime.h>
#include <cuda_fp16.h>
#include <mma.h>
#include <math.h>
#include <cstdint>

using namespace nvcuda;

#define B_SZ   128
#define KDIM   4096
#define EMB    512
#define NNEG   2048
#define OUTW   (NNEG + 1)

#define BK     32
#define LDH    40        // padded half-row (80B)
#define LDF    36        // padded f32-row for B staging (144B, conflict-free LDS.128)

// Dynamic SMEM layout (bytes)
#define SBF_STRIDE (128 * LDF * 4)       // 18432
#define SAH_STRIDE (128 * LDH * 2)       // 10240
#define SBF_OFF    0
#define SAH_OFF    (3 * SBF_STRIDE)                  // 55296
#define SBH_OFF    (SAH_OFF + 3 * SAH_STRIDE)        // 86016
#define SMEM_TOTAL (SBH_OFF + 2 * SAH_STRIDE)        // 106496

// Scratch (static device globals — no allocation).
__device__ float  g_part[4 * 1024 * 1024];    // 16 MB (f32 split-K partials)
__device__ __half g_vfs_h[B_SZ * KDIM];       // 1 MB
__device__ __half g_hidden_h[B_SZ * KDIM];    // 1 MB
__device__ __half g_nlfs_h[NNEG * EMB];       // 2 MB
__device__ float  g_emb[B_SZ * EMB];          // 256 KB (f32, for pscore)
__device__ __half g_emb_h[B_SZ * EMB];        // 128 KB (fp16, for nscore)

__device__ __forceinline__ uint32_t h2_bits(__half2 h) {
    return *reinterpret_cast<uint32_t*>(&h);
}
__device__ __forceinline__ __half2 b2h2(uint32_t u) {
    __half2 h; *reinterpret_cast<uint32_t*>(&h) = u; return h;
}
__device__ __forceinline__ uint32_t smem_u32(const void* p) {
    uint32_t a;
    asm("{ .reg .u64 t; cvta.to.shared.u64 t, %1; cvt.u32.u64 %0, t; }" : "=r"(a) : "l"(p));
    return a;
}

// One merged f32->fp16 conversion over vfs (65536 grps of 8) + n_lfs (131072).
__global__ void __launch_bounds__(256) cvt_all(
    const float* __restrict__ vfs, const float* __restrict__ nlfs,
    __half* __restrict__ vfs_h, __half* __restrict__ nlfs_h)
{
    int id = blockIdx.x * blockDim.x + threadIdx.x;     // < 196608
    const float* s; __half* d; int off;
    if (id < 65536) { s = vfs;  d = vfs_h;  off = id; }
    else            { s = nlfs; d = nlfs_h; off = id - 65536; }
    const float4* sp = (const float4*)s;
    float4 a = sp[off * 2], b = sp[off * 2 + 1];
    uint4 o;
    o.x = h2_bits(__floats2half2_rn(a.x, a.y));
    o.y = h2_bits(__floats2half2_rn(a.z, a.w));
    o.z = h2_bits(__floats2half2_rn(b.x, b.y));
    o.w = h2_bits(__floats2half2_rn(b.z, b.w));
    ((uint4*)d)[off] = o;
}

// ---------------------------------------------------------------------------
// fp16 WMMA split-K GEMM:
//   A fp16 -> cp.async (3-stage), B f32 -> cp.async (3-stage) -> SMEM cvt ->
//   fp16 (2-stage), f32 accumulate, direct f32 partial store. 2 CTAs/SM.
// Cpart[sk][128, N] = A[128, ksl] @ B[N, ksl]^T
// BM=128, BN=128, BK=32, 256 threads (8 warps 2x4), warp tile 64x32.
// ---------------------------------------------------------------------------
__device__ __forceinline__ void cp_A(const __half* __restrict__ A, char* smem,
                                     int s, int k0, int tid)
{
    __half* sA = (__half*)(smem + SAH_OFF + s * SAH_STRIDE);
    #pragma unroll
    for (int i = 0; i < 2; i++) {
        int id = tid + i * 256;            // 0..511 16B chunks
        int row = id >> 2;
        int seg = (id & 3) << 3;           // halves
        uint32_t d = smem_u32(&sA[row * LDH + seg]);
        const __half* g = &A[(size_t)row * KDIM + k0 + seg];
        asm volatile("cp.async.cg.shared.global [%0], [%1], 16;" :: "r"(d), "l"(g) : "memory");
    }
}

__device__ __forceinline__ void cp_Bf(const float* __restrict__ B, char* smem,
                                      int s, int k0, int tid, int nbase)
{
    float* sBf = (float*)(smem + SBF_OFF + s * SBF_STRIDE);
    #pragma unroll
    for (int i = 0; i < 4; i++) {
        int id = tid + i * 256;            // 0..1023 16B chunks (8 per row)
        int row = id >> 3;
        int c = (id & 7) << 2;             // float offset
        uint32_t d = smem_u32(&sBf[row * LDF + c]);
        const float* g = &B[(size_t)(nbase + row) * KDIM + k0 + c];
        asm volatile("cp.async.cg.shared.global [%0], [%1], 16;" :: "r"(d), "l"(g) : "memory");
    }
}

// SMEM f32 -> SMEM fp16 convert (16 floats per thread, conflict-free LDS.128)
__device__ __forceinline__ void cvt_b(char* smem, int s, int p, int tid)
{
    const float* src = (const float*)(smem + SBF_OFF + s * SBF_STRIDE);
    __half* dst = (__half*)(smem + SBH_OFF + p * SAH_STRIDE);
    const int row = tid >> 1;
    const int seg = (tid & 1) << 4;
    const float* q = src + row * LDF + seg;
    float4 v0 = *(const float4*)(q);
    float4 v1 = *(const float4*)(q + 4);
    float4 v2 = *(const float4*)(q + 8);
    float4 v3 = *(const float4*)(q + 12);
    uint4 w0, w1;
    w0.x = h2_bits(__floats2half2_rn(v0.x, v0.y));
    w0.y = h2_bits(__floats2half2_rn(v0.z, v0.w));
    w0.z = h2_bits(__floats2half2_rn(v1.x, v1.y));
    w0.w = h2_bits(__floats2half2_rn(v1.z, v1.w));
    w1.x = h2_bits(__floats2half2_rn(v2.x, v2.y));
    w1.y = h2_bits(__floats2half2_rn(v2.z, v2.w));
    w1.z = h2_bits(__floats2half2_rn(v3.x, v3.y));
    w1.w = h2_bits(__floats2half2_rn(v3.z, v3.w));
    *(uint4*)&dst[row * LDH + seg]     = w0;
    *(uint4*)&dst[row * LDH + seg + 8] = w1;
}

__global__ void __launch_bounds__(256, 2)
hgemm(const __half* __restrict__ A, const float* __restrict__ B,
      float* __restrict__ C, int ldc, int k_len)
{
    extern __shared__ __align__(16) char smem[];

    const int tid = threadIdx.x;
    const int wid = tid >> 5;
    const int wm = wid >> 2, wn = wid & 3;
    const int nbase = blockIdx.x * 128;
    const int k_lo = blockIdx.y * k_len;
    float* __restrict__ Cout = C + (size_t)blockIdx.y * 128u * (size_t)ldc;

    wmma::fragment<wmma::accumulator, 16, 16, 16, float> acc[4][2];
    #pragma unroll
    for (int i = 0; i < 4; i++)
        #pragma unroll
        for (int j = 0; j < 2; j++) wmma::fill_fragment(acc[i][j], 0.0f);

    const int nIter = k_len / BK;

    // prologue: 3 groups in flight
    #pragma unroll
    for (int s = 0; s < 3; s++) {
        if (s < nIter) {
            cp_A(A, smem, s, k_lo + s * BK, tid);
            cp_Bf(B, smem, s, k_lo + s * BK, tid, nbase);
        }
        asm volatile("cp.async.commit_group;" ::: "memory");
    }
    asm volatile("cp.async.wait_group 2;" ::: "memory");
    __syncthreads();
    cvt_b(smem, 0, 0, tid);
    __syncthreads();

    for (int it = 0; it < nIter; it++) {
        const int p = it & 1;
        const __half* sA = (const __half*)(smem + SAH_OFF + (it % 3) * SAH_STRIDE);
        const __half* sB = (const __half*)(smem + SBH_OFF + p * SAH_STRIDE);

        #pragma unroll
        for (int ks = 0; ks < 2; ks++) {
            const int k0 = ks * 16;
            wmma::fragment<wmma::matrix_a, 16, 16, 16, __half, wmma::row_major> af[4];
            wmma::fragment<wmma::matrix_b, 16, 16, 16, __half, wmma::col_major> bf[2];
            #pragma unroll
            for (int i = 0; i < 4; i++)
                wmma::load_matrix_sync(af[i], &sA[(wm * 64 + i * 16) * LDH + k0], LDH);
            #pragma unroll
            for (int j = 0; j < 2; j++)
                wmma::load_matrix_sync(bf[j], &sB[(wn * 32 + j * 16) * LDH + k0], LDH);
            #pragma unroll
            for (int i = 0; i < 4; i++)
                #pragma unroll
                for (int j = 0; j < 2; j++)
                    wmma::mma_sync(acc[i][j], af[i], bf[j], acc[i][j]);
        }

        if (it + 1 < nIter) {
            __syncthreads();                       // mma(it) done: stage it%3 free
            if (it + 3 < nIter) {
                cp_A(A, smem, (it + 3) % 3, k_lo + (it + 3) * BK, tid);
                cp_Bf(B, smem, (it + 3) % 3, k_lo + (it + 3) * BK, tid, nbase);
            }
            asm volatile("cp.async.commit_group;" ::: "memory");
            asm volatile("cp.async.wait_group 2;" ::: "memory");   // grp(it+1) done
            cvt_b(smem, (it + 1) % 3, p ^ 1, tid);
            __syncthreads();                       // bh(it+1) visible
        }
    }

    #pragma unroll
    for (int i = 0; i < 4; i++)
        #pragma unroll
        for (int j = 0; j < 2; j++)
            wmma::store_matrix_sync(&Cout[(size_t)(wm * 64 + i * 16) * ldc + nbase + wn * 32 + j * 16],
                                    acc[i][j], ldc, wmma::mem_row_major);
}

// hidden(fp16) = sum_{sk<8} part[sk] + b_h.
__global__ void __launch_bounds__(256) reduce_hidden(const float* __restrict__ b_h) {
    int g = blockIdx.x * blockDim.x + threadIdx.x;     // < 262144
    int o = g >> 1, h = g & 1;
    float4 s = make_float4(0.f, 0.f, 0.f, 0.f);
    #pragma unroll
    for (int k = 0; k < 4; k++) {
        float4 v = *(const float4*)&g_part[(size_t)(h * 4 + k) * (B_SZ * KDIM) + (size_t)o * 4];
        s.x += v.x; s.y += v.y; s.z += v.z; s.w += v.w;
    }
    float4 oth;
    oth.x = __shfl_xor_sync(0xffffffffu, s.x, 1);
    oth.y = __shfl_xor_sync(0xffffffffu, s.y, 1);
    oth.z = __shfl_xor_sync(0xffffffffu, s.z, 1);
    oth.w = __shfl_xor_sync(0xffffffffu, s.w, 1);
    if (h == 0) {
        float4 bias = ((const float4*)b_h)[o & (KDIM / 4 - 1)];
        uint2 w;
        w.x = h2_bits(__floats2half2_rn(s.x + oth.x + bias.x, s.y + oth.y + bias.y));
        w.y = h2_bits(__floats2half2_rn(s.z + oth.z + bias.z, s.w + oth.w + bias.w));
        ((uint2*)g_hidden_h)[o] = w;
    }
}

// emb = sum_{sk<32} part[sk] + b_e.  Writes f32 (pscore) and fp16 (nscore).
__global__ void __launch_bounds__(256) reduce_emb(const float* __restrict__ b_e) {
    __shared__ float4 red[8][32];
    const int lane = threadIdx.x & 31;
    const int w = threadIdx.x >> 5;
    const int o = blockIdx.x * 32 + lane;
    float4 s = make_float4(0.f, 0.f, 0.f, 0.f);
    #pragma unroll
    for (int k = 0; k < 4; k++) {
        float4 v = *(const float4*)&g_part[(size_t)(w * 4 + k) * (B_SZ * EMB) + (size_t)o * 4];
        s.x += v.x; s.y += v.y; s.z += v.z; s.w += v.w;
    }
    red[w][lane] = s;
    __syncthreads();
    if (w == 0) {
        float4 r = ((const float4*)b_e)[o & (EMB / 4 - 1)];
        #pragma unroll
        for (int k = 0; k < 8; k++) {
            float4 v = red[k][lane];
            r.x += v.x; r.y += v.y; r.z += v.z; r.w += v.w;
        }
        ((float4*)g_emb)[o] = r;
        uint2 hh;
        hh.x = h2_bits(__floats2half2_rn(r.x, r.y));
        hh.y = h2_bits(__floats2half2_rn(r.z, r.w));
        ((uint2*)g_emb_h)[o] = hh;
    }
}

// out[b, 1+n] = -||relu(n - emb)||  (fp16 half2 math, f32 chunk accumulation);
// blocks with bx==16 do positive scores in f32.
__global__ void __launch_bounds__(256, 2)
nscore_kernel(const float* __restrict__ p_lfs, float* __restrict__ out) {
    const int tid = threadIdx.x;
    const int btile = blockIdx.y * 16;

    if (blockIdx.x == 16) {   // positive-score path: 8 warps x 2 b each (f32)
        int wq = tid >> 5, lane = tid & 31;
        #pragma unroll
        for (int r = 0; r < 2; r++) {
            int b = btile + wq * 2 + r;
            const float* pp = p_lfs + (size_t)b * EMB;
            const float* ee = g_emb + (size_t)b * EMB;
            float s = 0.f;
            #pragma unroll
            for (int j = 0; j < 4; j++) {
                int d = j * 128 + lane * 4;
                float4 p = *(const float4*)&pp[d];
                float4 e = *(const float4*)&ee[d];
                float r0 = fmaxf(p.x - e.x, 0.f), r1 = fmaxf(p.y - e.y, 0.f);
                float r2 = fmaxf(p.z - e.z, 0.f), r3 = fmaxf(p.w - e.w, 0.f);
                s = fmaf(r0, r0, s); s = fmaf(r1, r1, s);
                s = fmaf(r2, r2, s); s = fmaf(r3, r3, s);
            }
            #pragma unroll
            for (int off = 16; off > 0; off >>= 1) s += __shfl_down_sync(0xffffffffu, s, off);
            if (lane == 0) out[(size_t)b * OUTW] = -sqrtf(s);
        }
        return;
    }

    __shared__ __half2 Ns2[16][132];   // [d-pair][n]
    __shared__ __half2 Es2[16][16];    // [b][d-pair]
    const int tx = tid & 31;
    const int bq = tid >> 5;
    const int nbase = blockIdx.x * 128;

    float facc[2][4] = {};
    uint4 nR[2];
    uint2 eR = make_uint2(0u, 0u);
    const int erow = tid >> 3, edp = (tid & 7) * 2;    // Es: 16 rows x 8 thr

    #pragma unroll
    for (int i = 0; i < 2; i++) {
        int f = tid + i * 256;
        int row = f >> 2, seg = (f & 3) * 8;           // dims
        nR[i] = *(const uint4*)&g_nlfs_h[(size_t)(nbase + row) * EMB + seg];
    }
    if (tid < 128)
        eR = *(const uint2*)&g_emb_h[(size_t)(btile + erow) * EMB + edp * 2];

    for (int it = 0; it < 16; it++) {
        #pragma unroll
        for (int i = 0; i < 2; i++) {
            int f = tid + i * 256;
            int row = f >> 2, dp0 = (f & 3) * 4;
            Ns2[dp0 + 0][row] = b2h2(nR[i].x);
            Ns2[dp0 + 1][row] = b2h2(nR[i].y);
            Ns2[dp0 + 2][row] = b2h2(nR[i].z);
            Ns2[dp0 + 3][row] = b2h2(nR[i].w);
        }
        if (tid < 128) {
            Es2[erow][edp]     = b2h2(eR.x);
            Es2[erow][edp + 1] = b2h2(eR.y);
        }
        __syncthreads();
        if (it + 1 < 16) {
            int dc = (it + 1) * 32;
            #pragma unroll
            for (int i = 0; i < 2; i++) {
                int f = tid + i * 256;
                int row = f >> 2, seg = (f & 3) * 8;
                nR[i] = *(const uint4*)&g_nlfs_h[(size_t)(nbase + row) * EMB + dc + seg];
            }
            if (tid < 128)
                eR = *(const uint2*)&g_emb_h[(size_t)(btile + erow) * EMB + dc + edp * 2];
        }

        const __half2 hz = __float2half2_rn(0.f);
        __half2 hacc[2][4];
        #pragma unroll
        for (int i = 0; i < 2; i++)
            #pragma unroll
            for (int j = 0; j < 4; j++) hacc[i][j] = hz;

        #pragma unroll
        for (int d = 0; d < 16; d++) {
            __half2 e0 = Es2[bq * 2 + 0][d];
            __half2 e1 = Es2[bq * 2 + 1][d];
            uint4 nv = *(const uint4*)&Ns2[d][tx * 4];
            __half2 n0 = b2h2(nv.x), n1 = b2h2(nv.y), n2 = b2h2(nv.z), n3 = b2h2(nv.w);
            __half2 t;
            t = __hmax2(__hsub2(n0, e0), hz); hacc[0][0] = __hfma2(t, t, hacc[0][0]);
            t = __hmax2(__hsub2(n1, e0), hz); hacc[0][1] = __hfma2(t, t, hacc[0][1]);
            t = __hmax2(__hsub2(n2, e0), hz); hacc[0][2] = __hfma2(t, t, hacc[0][2]);
            t = __hmax2(__hsub2(n3, e0), hz); hacc[0][3] = __hfma2(t, t, hacc[0][3]);
            t = __hmax2(__hsub2(n0, e1), hz); hacc[1][0] = __hfma2(t, t, hacc[1][0]);
            t = __hmax2(__hsub2(n1, e1), hz); hacc[1][1] = __hfma2(t, t, hacc[1][1]);
            t = __hmax2(__hsub2(n2, e1), hz); hacc[1][2] = __hfma2(t, t, hacc[1][2]);
            t = __hmax2(__hsub2(n3, e1), hz); hacc[1][3] = __hfma2(t, t, hacc[1][3]);
        }
        __syncthreads();

        #pragma unroll
        for (int i = 0; i < 2; i++)
            #pragma unroll
            for (int j = 0; j < 4; j++) {
                float2 f = __half22float2(hacc[i][j]);
                facc[i][j] += f.x + f.y;
            }
    }

    #pragma unroll
    for (int bi = 0; bi < 2; bi++) {
        int b = btile + bq * 2 + bi;
        #pragma unroll
        for (int j = 0; j < 4; j++)
            out[(size_t)b * OUTW + 1 + nbase + tx * 4 + j] = -sqrtf(facc[bi][j]);
    }
}

extern "C" void kernel_launch(void* const* d_in, const int* in_sizes, int n_in,
                              void* d_out, int out_size) {
    const float* vfs   = (const float*)d_in[0];
    const float* p_lfs = (const float*)d_in[1];
    const float* n_lfs = (const float*)d_in[2];
    const float* W_h   = (const float*)d_in[3];
    const float* b_h   = (const float*)d_in[4];
    const float* W_e   = (const float*)d_in[5];
    const float* b_e   = (const float*)d_in[6];
    float* out = (float*)d_out;

    float* part = nullptr;
    __half *vfs_h = nullptr, *hidden_h = nullptr, *nlfs_h = nullptr;
    cudaGetSymbolAddress((void**)&part, g_part);
    cudaGetSymbolAddress((void**)&vfs_h, g_vfs_h);
    cudaGetSymbolAddress((void**)&hidden_h, g_hidden_h);
    cudaGetSymbolAddress((void**)&nlfs_h, g_nlfs_h);

    static bool attr_set = false;
    if (!attr_set) {
        cudaFuncSetAttribute(hgemm, cudaFuncAttributeMaxDynamicSharedMemorySize, SMEM_TOTAL);
        attr_set = true;
    }

    // merged fp16 pre-conversion: vfs + n_lfs (1 launch, 768 blocks)
    cvt_all<<<768, 256>>>(vfs, n_lfs, vfs_h, nlfs_h);
    // GEMM1: part[8][128][4096] = vfs_h @ W_h^T  (K-split 8 -> 256 CTAs)
    hgemm<<<dim3(KDIM / 128, 8), 256, SMEM_TOTAL>>>(vfs_h, W_h, part, KDIM, KDIM / 8);
    reduce_hidden<<<1024, 256>>>(b_h);
    // GEMM2: part[32][128][512] = hidden_h @ W_e^T (K-split 32 -> 128 CTAs)
    hgemm<<<dim3(EMB / 128, 32), 256, SMEM_TOTAL>>>(hidden_h, W_e, part, EMB, KDIM / 32);
    reduce_emb<<<512, 256>>>(b_e);
    // scores (bx==16 blocks do positive scores)
    nscore_kernel<<<dim3(NNEG / 128 + 1, B_SZ / 16), 256>>>(p_lfs, out);
}